// round 6
// baseline (speedup 1.0000x reference)
#include <cuda_runtime.h>
#include <stdint.h>

#define N_NODES 50000
#define N_EDGES 600000
#define IN_C    128
#define HID_C   128
#define OUT_C   64

// ----------------- device scratch (no allocations allowed) -----------------
__device__ int   g_flag;                 // 1 => edge_index is int64
__device__ int   g_src[N_EDGES];
__device__ int   g_dst[N_EDGES];
__device__ int   g_count[N_NODES];
__device__ int   g_cursor[N_NODES];
__device__ int   g_rowptr[N_NODES + 1];
__device__ int   g_adj[N_EDGES];
__device__ float g_dinv[N_NODES];
__device__ __align__(16) float g_h0[(size_t)N_NODES * HID_C];
__device__ __align__(16) float g_h1[(size_t)N_NODES * HID_C];
__device__ __align__(16) float g_h2[(size_t)N_NODES * OUT_C];

// ----------------- JAX threefry2x32 dropout mask ---------------------------
// jax.random.bernoulli(key(42), 0.5, (N, HID)) keeps element with flat index i
// iff top bit of random_bits(i) == 0.
// Partitionable scheme (modern JAX default): counter = (hi=0, lo=i),
// 32-bit bits = out0 XOR out1 of threefry2x32 (see
// _threefry_random_bits_partitionable: bit_width==32 -> bits1 ^ bits2).
__device__ __forceinline__ uint32_t tf_rotl(uint32_t x, int r) {
    return __funnelshift_l(x, x, r);
}

__device__ __forceinline__ uint32_t tf_bits(uint32_t idx) {
    const uint32_t k0 = 0u, k1 = 42u;
    const uint32_t k2 = 0x1BD11BDAu ^ k0 ^ k1;
    uint32_t x0 = 0u + k0;     // hi counter word = 0 (size < 2^32)
    uint32_t x1 = idx + k1;
#define TF_R4(a, b, c, d)                                   \
    x0 += x1; x1 = tf_rotl(x1, a); x1 ^= x0;                \
    x0 += x1; x1 = tf_rotl(x1, b); x1 ^= x0;                \
    x0 += x1; x1 = tf_rotl(x1, c); x1 ^= x0;                \
    x0 += x1; x1 = tf_rotl(x1, d); x1 ^= x0;
    TF_R4(13, 15, 26, 6);  x0 += k1; x1 += k2 + 1u;
    TF_R4(17, 29, 16, 24); x0 += k2; x1 += k0 + 2u;
    TF_R4(13, 15, 26, 6);  x0 += k0; x1 += k1 + 3u;
    TF_R4(17, 29, 16, 24); x0 += k1; x1 += k2 + 4u;
    TF_R4(13, 15, 26, 6);  x0 += k2; x1 += k0 + 5u;
#undef TF_R4
    return x0 ^ x1;   // <-- 32-bit partitionable draw is the XOR of both words
}

__device__ __forceinline__ float apply_dropout(float v, uint32_t flat) {
    uint32_t bits = tf_bits(flat);
    // u < 0.5  <=>  top bit of bits == 0 ; keep => v / (1-p) = v * 2
    return (bits & 0x80000000u) ? 0.0f : v * 2.0f;
}

// ----------------- small setup kernels --------------------------------------
__global__ void detect_kernel(const int* __restrict__ ei) {
    if (threadIdx.x == 0 && blockIdx.x == 0) {
        int all_zero = 1;
        for (int i = 1; i < 128; i += 2)
            if (ei[i] != 0) all_zero = 0;
        g_flag = all_zero;
    }
}

__global__ void zero_count_kernel() {
    int n = blockIdx.x * blockDim.x + threadIdx.x;
    if (n < N_NODES) g_count[n] = 0;
}

__global__ void convert_kernel(const void* __restrict__ ei) {
    int e = blockIdx.x * blockDim.x + threadIdx.x;
    if (e >= N_EDGES) return;
    int s, d;
    if (g_flag) {
        const long long* p = (const long long*)ei;
        s = (int)p[e];
        d = (int)p[e + N_EDGES];
    } else {
        const int* p = (const int*)ei;
        s = p[e];
        d = p[e + N_EDGES];
    }
    g_src[e] = s;
    g_dst[e] = d;
    atomicAdd(&g_count[d], 1);
}

__global__ void dinv_kernel() {
    int n = blockIdx.x * blockDim.x + threadIdx.x;
    if (n < N_NODES) g_dinv[n] = rsqrtf(1.0f + (float)g_count[n]);
}

// exclusive scan of g_count -> g_rowptr, single block of 1024 threads
__global__ void scan_kernel() {
    const int T = 1024;
    const int C = (N_NODES + T - 1) / T;  // 49
    int t = threadIdx.x;
    int base = t * C;

    int s = 0;
    for (int i = 0; i < C; i++) {
        int idx = base + i;
        if (idx < N_NODES) s += g_count[idx];
    }

    __shared__ int wsum[32];
    int lane = t & 31, wid = t >> 5;
    int v = s;
#pragma unroll
    for (int o = 1; o < 32; o <<= 1) {
        int u = __shfl_up_sync(0xFFFFFFFFu, v, o);
        if (lane >= o) v += u;
    }
    if (lane == 31) wsum[wid] = v;
    __syncthreads();
    if (wid == 0) {
        int w = wsum[lane];
#pragma unroll
        for (int o = 1; o < 32; o <<= 1) {
            int u = __shfl_up_sync(0xFFFFFFFFu, w, o);
            if (lane >= o) w += u;
        }
        wsum[lane] = w;
    }
    __syncthreads();
    int excl = v - s + (wid > 0 ? wsum[wid - 1] : 0);

    int run = excl;
    for (int i = 0; i < C; i++) {
        int idx = base + i;
        if (idx < N_NODES) {
            g_rowptr[idx] = run;
            run += g_count[idx];
        }
    }
    if (t == T - 1) g_rowptr[N_NODES] = run;

    // zero cursors for the fill pass
    for (int idx = t; idx < N_NODES; idx += T) g_cursor[idx] = 0;
}

__global__ void fill_kernel() {
    int e = blockIdx.x * blockDim.x + threadIdx.x;
    if (e >= N_EDGES) return;
    int d = g_dst[e];
    int pos = atomicAdd(&g_cursor[d], 1);
    g_adj[g_rowptr[d] + pos] = g_src[e];
}

// ----------------- SGEMM: C[M,N] = A[M,K] @ B[K,N] --------------------------
// BM=128, BK=16, TM=8; BN/TN templated (128/8 for layer1, 64/4 for layer2)
template <int BN, int TN>
__global__ __launch_bounds__(256) void sgemm_kernel(
    const float* __restrict__ A, const float* __restrict__ B,
    float* __restrict__ C, int M, int N, int K)
{
    constexpr int BM = 128, BK = 16, TM = 8;
    constexpr int TX = BN / TN;  // 16
    __shared__ float As[BK][BM];
    __shared__ float Bs[BK][BN];

    int tid = threadIdx.x;
    int tx = tid % TX;
    int ty = tid / TX;
    int rowBase = blockIdx.x * BM;

    float acc[TM][TN];
#pragma unroll
    for (int i = 0; i < TM; i++)
#pragma unroll
        for (int j = 0; j < TN; j++) acc[i][j] = 0.0f;

    for (int k0 = 0; k0 < K; k0 += BK) {
        // load A tile: 128x16 = 512 float4, 2 per thread
#pragma unroll
        for (int i = 0; i < 2; i++) {
            int q = tid + i * 256;
            int m = q >> 2;
            int kq = (q & 3) * 4;
            float4 v = make_float4(0.f, 0.f, 0.f, 0.f);
            int gm = rowBase + m;
            if (gm < M) v = *(const float4*)&A[(size_t)gm * K + k0 + kq];
            As[kq + 0][m] = v.x;
            As[kq + 1][m] = v.y;
            As[kq + 2][m] = v.z;
            As[kq + 3][m] = v.w;
        }
        // load B tile: BK x BN floats
        constexpr int BLOADS = (BK * BN / 4) / 256;  // 2 for BN=128, 1 for BN=64
#pragma unroll
        for (int i = 0; i < BLOADS; i++) {
            int q = tid + i * 256;
            int kk = q / (BN / 4);
            int nq = (q % (BN / 4)) * 4;
            float4 v = *(const float4*)&B[(size_t)(k0 + kk) * N + nq];
            *(float4*)&Bs[kk][nq] = v;
        }
        __syncthreads();

#pragma unroll
        for (int kk = 0; kk < BK; kk++) {
            float ra[TM], rb[TN];
#pragma unroll
            for (int i = 0; i < TM; i++) ra[i] = As[kk][ty * TM + i];
#pragma unroll
            for (int j = 0; j < TN; j++) rb[j] = Bs[kk][tx * TN + j];
#pragma unroll
            for (int i = 0; i < TM; i++)
#pragma unroll
                for (int j = 0; j < TN; j++)
                    acc[i][j] = fmaf(ra[i], rb[j], acc[i][j]);
        }
        __syncthreads();
    }

#pragma unroll
    for (int i = 0; i < TM; i++) {
        int gm = rowBase + ty * TM + i;
        if (gm < M) {
#pragma unroll
            for (int j = 0; j < TN; j += 4) {
                *(float4*)&C[(size_t)gm * N + tx * TN + j] =
                    make_float4(acc[i][j], acc[i][j + 1], acc[i][j + 2], acc[i][j + 3]);
            }
        }
    }
}

// ----------------- aggregation layer 1: bias + relu + dropout fused ---------
// one warp per node, each lane owns a float4 (4 channels)
__global__ void agg1_kernel(const float* __restrict__ b1) {
    int w = (blockIdx.x * blockDim.x + threadIdx.x) >> 5;
    int lane = threadIdx.x & 31;
    if (w >= N_NODES) return;
    int n = w;

    float dn = g_dinv[n];
    const float4* h0 = (const float4*)g_h0;

    float4 a = h0[(size_t)n * 32 + lane];
    float wn = dn * dn;
    float4 acc = make_float4(a.x * wn, a.y * wn, a.z * wn, a.w * wn);

    int beg = g_rowptr[n], end = g_rowptr[n + 1];
    for (int k = beg; k < end; k++) {
        int s = g_adj[k];
        float we = g_dinv[s] * dn;
        float4 v = h0[(size_t)s * 32 + lane];
        acc.x = fmaf(we, v.x, acc.x);
        acc.y = fmaf(we, v.y, acc.y);
        acc.z = fmaf(we, v.z, acc.z);
        acc.w = fmaf(we, v.w, acc.w);
    }

    float4 bb = *(const float4*)&b1[lane * 4];
    acc.x = fmaxf(acc.x + bb.x, 0.0f);
    acc.y = fmaxf(acc.y + bb.y, 0.0f);
    acc.z = fmaxf(acc.z + bb.z, 0.0f);
    acc.w = fmaxf(acc.w + bb.w, 0.0f);

    uint32_t flat = (uint32_t)n * HID_C + lane * 4;
    acc.x = apply_dropout(acc.x, flat + 0);
    acc.y = apply_dropout(acc.y, flat + 1);
    acc.z = apply_dropout(acc.z, flat + 2);
    acc.w = apply_dropout(acc.w, flat + 3);

    ((float4*)g_h1)[(size_t)n * 32 + lane] = acc;
}

// ----------------- aggregation layer 2: bias fused, writes d_out ------------
// one warp per node, each lane owns a float2 (2 of 64 channels)
__global__ void agg2_kernel(const float* __restrict__ b2, float* __restrict__ out) {
    int w = (blockIdx.x * blockDim.x + threadIdx.x) >> 5;
    int lane = threadIdx.x & 31;
    if (w >= N_NODES) return;
    int n = w;

    float dn = g_dinv[n];
    const float2* h2 = (const float2*)g_h2;

    float2 a = h2[(size_t)n * 32 + lane];
    float wn = dn * dn;
    float2 acc = make_float2(a.x * wn, a.y * wn);

    int beg = g_rowptr[n], end = g_rowptr[n + 1];
    for (int k = beg; k < end; k++) {
        int s = g_adj[k];
        float we = g_dinv[s] * dn;
        float2 v = h2[(size_t)s * 32 + lane];
        acc.x = fmaf(we, v.x, acc.x);
        acc.y = fmaf(we, v.y, acc.y);
    }

    float2 bb = *(const float2*)&b2[lane * 2];
    acc.x += bb.x;
    acc.y += bb.y;
    ((float2*)out)[(size_t)n * 32 + lane] = acc;
}

// ----------------- launch ----------------------------------------------------
extern "C" void kernel_launch(void* const* d_in, const int* in_sizes, int n_in,
                              void* d_out, int out_size) {
    const float* x  = (const float*)d_in[0];   // [50000,128]
    const float* W1 = (const float*)d_in[1];   // [128,128]
    const float* b1 = (const float*)d_in[2];   // [128]
    const float* W2 = (const float*)d_in[3];   // [128,64]
    const float* b2 = (const float*)d_in[4];   // [64]
    const void*  ei = (const void*)d_in[5];    // [2,600000] int32 or int64
    float* out = (float*)d_out;

    // graph build
    detect_kernel<<<1, 32>>>((const int*)ei);
    zero_count_kernel<<<(N_NODES + 255) / 256, 256>>>();
    convert_kernel<<<(N_EDGES + 255) / 256, 256>>>(ei);
    dinv_kernel<<<(N_NODES + 255) / 256, 256>>>();
    scan_kernel<<<1, 1024>>>();
    fill_kernel<<<(N_EDGES + 255) / 256, 256>>>();

    float* h0 = nullptr; cudaGetSymbolAddress((void**)&h0, g_h0);
    float* h1 = nullptr; cudaGetSymbolAddress((void**)&h1, g_h1);
    float* h2 = nullptr; cudaGetSymbolAddress((void**)&h2, g_h2);

    // layer 1: h0 = x @ W1 ; agg + bias + relu + dropout -> h1
    sgemm_kernel<128, 8><<<(N_NODES + 127) / 128, 256>>>(x, W1, h0, N_NODES, HID_C, IN_C);
    agg1_kernel<<<(N_NODES * 32 + 255) / 256, 256>>>(b1);

    // layer 2: h2 = h1 @ W2 ; agg + bias -> out
    sgemm_kernel<64, 4><<<(N_NODES + 127) / 128, 256>>>(h1, W2, h2, N_NODES, OUT_C, HID_C);
    agg2_kernel<<<(N_NODES * 32 + 255) / 256, 256>>>(b2, out);
}

// round 13
// speedup vs baseline: 1.1464x; 1.1464x over previous
#include <cuda_runtime.h>
#include <stdint.h>

#define N_NODES 50000
#define N_EDGES 600000
#define IN_C    128
#define HID_C   128
#define OUT_C   64

// ----------------- device scratch (no allocations allowed) -----------------
__device__ int   g_flag;                 // 1 => edge_index is int64
__device__ int   g_src[N_EDGES];
__device__ int   g_dst[N_EDGES];
__device__ int   g_count[N_NODES];
__device__ int   g_cursor[N_NODES];
__device__ int   g_rowptr[N_NODES + 1];
__device__ int   g_adj[N_EDGES];
__device__ float g_dinv[N_NODES];
__device__ __align__(16) float g_W1T[HID_C * IN_C];   // W1^T [N=128][K=128], tf32-rounded
__device__ __align__(16) float g_W2T[OUT_C * HID_C];  // W2^T [N=64][K=128], tf32-rounded
__device__ __align__(16) float g_h0[(size_t)N_NODES * HID_C];
__device__ __align__(16) float g_h1[(size_t)N_NODES * HID_C];
__device__ __align__(16) float g_h2[(size_t)N_NODES * OUT_C];

// ----------------- tf32 helpers ---------------------------------------------
__device__ __forceinline__ float to_tf32(float x) {
    float y;
    asm("cvt.rna.tf32.f32 %0, %1;" : "=f"(y) : "f"(x));
    return y;
}

// m16n8k8 tf32 MMA (sm_80+ PTX, runs on tensor pipe, no 'a'-gated features)
__device__ __forceinline__ void mma_16x8x8(float* c, const uint32_t* a, const uint32_t* b) {
    asm volatile(
        "mma.sync.aligned.m16n8k8.row.col.f32.tf32.tf32.f32 "
        "{%0,%1,%2,%3}, {%4,%5,%6,%7}, {%8,%9}, {%0,%1,%2,%3};"
        : "+f"(c[0]), "+f"(c[1]), "+f"(c[2]), "+f"(c[3])
        : "r"(a[0]), "r"(a[1]), "r"(a[2]), "r"(a[3]), "r"(b[0]), "r"(b[1]));
}

// ----------------- JAX threefry2x32 dropout mask ---------------------------
__device__ __forceinline__ uint32_t tf_rotl(uint32_t x, int r) {
    return __funnelshift_l(x, x, r);
}

__device__ __forceinline__ uint32_t tf_bits(uint32_t idx) {
    const uint32_t k0 = 0u, k1 = 42u;
    const uint32_t k2 = 0x1BD11BDAu ^ k0 ^ k1;
    uint32_t x0 = 0u + k0;
    uint32_t x1 = idx + k1;
#define TF_R4(a, b, c, d)                                   \
    x0 += x1; x1 = tf_rotl(x1, a); x1 ^= x0;                \
    x0 += x1; x1 = tf_rotl(x1, b); x1 ^= x0;                \
    x0 += x1; x1 = tf_rotl(x1, c); x1 ^= x0;                \
    x0 += x1; x1 = tf_rotl(x1, d); x1 ^= x0;
    TF_R4(13, 15, 26, 6);  x0 += k1; x1 += k2 + 1u;
    TF_R4(17, 29, 16, 24); x0 += k2; x1 += k0 + 2u;
    TF_R4(13, 15, 26, 6);  x0 += k0; x1 += k1 + 3u;
    TF_R4(17, 29, 16, 24); x0 += k1; x1 += k2 + 4u;
    TF_R4(13, 15, 26, 6);  x0 += k2; x1 += k0 + 5u;
#undef TF_R4
    return x0 ^ x1;   // 32-bit partitionable draw = XOR of both output words
}

__device__ __forceinline__ float apply_dropout(float v, uint32_t flat) {
    uint32_t bits = tf_bits(flat);
    return (bits & 0x80000000u) ? 0.0f : v * 2.0f;
}

// ----------------- setup kernels --------------------------------------------
__global__ void setup0_kernel(const int* __restrict__ ei) {
    int n = blockIdx.x * blockDim.x + threadIdx.x;
    if (n < N_NODES) g_count[n] = 0;
    if (blockIdx.x == 0 && threadIdx.x == 0) {
        int all_zero = 1;
        for (int i = 1; i < 128; i += 2)
            if (ei[i] != 0) all_zero = 0;
        g_flag = all_zero;
    }
}

__global__ void convert_kernel(const void* __restrict__ ei) {
    int e = blockIdx.x * blockDim.x + threadIdx.x;
    if (e >= N_EDGES) return;
    int s, d;
    if (g_flag) {
        const long long* p = (const long long*)ei;
        s = (int)p[e];
        d = (int)p[e + N_EDGES];
    } else {
        const int* p = (const int*)ei;
        s = p[e];
        d = p[e + N_EDGES];
    }
    g_src[e] = s;
    g_dst[e] = d;
    atomicAdd(&g_count[d], 1);
}

// exclusive scan of g_count -> g_rowptr; also g_dinv and cursor zeroing
__global__ void scan_kernel() {
    const int T = 1024;
    const int C = (N_NODES + T - 1) / T;  // 49
    int t = threadIdx.x;
    int base = t * C;

    int s = 0;
    for (int i = 0; i < C; i++) {
        int idx = base + i;
        if (idx < N_NODES) s += g_count[idx];
    }

    __shared__ int wsum[32];
    int lane = t & 31, wid = t >> 5;
    int v = s;
#pragma unroll
    for (int o = 1; o < 32; o <<= 1) {
        int u = __shfl_up_sync(0xFFFFFFFFu, v, o);
        if (lane >= o) v += u;
    }
    if (lane == 31) wsum[wid] = v;
    __syncthreads();
    if (wid == 0) {
        int w = wsum[lane];
#pragma unroll
        for (int o = 1; o < 32; o <<= 1) {
            int u = __shfl_up_sync(0xFFFFFFFFu, w, o);
            if (lane >= o) w += u;
        }
        wsum[lane] = w;
    }
    __syncthreads();
    int excl = v - s + (wid > 0 ? wsum[wid - 1] : 0);

    int run = excl;
    for (int i = 0; i < C; i++) {
        int idx = base + i;
        if (idx < N_NODES) {
            g_rowptr[idx] = run;
            run += g_count[idx];
        }
    }
    if (t == T - 1) g_rowptr[N_NODES] = run;

    for (int idx = t; idx < N_NODES; idx += T) {
        g_cursor[idx] = 0;
        g_dinv[idx] = rsqrtf(1.0f + (float)g_count[idx]);
    }
}

__global__ void fill_kernel() {
    int e = blockIdx.x * blockDim.x + threadIdx.x;
    if (e >= N_EDGES) return;
    int d = g_dst[e];
    int pos = atomicAdd(&g_cursor[d], 1);
    g_adj[g_rowptr[d] + pos] = g_src[e];
}

// transpose + tf32-round the weights
__global__ void wtrans_kernel(const float* __restrict__ W1, const float* __restrict__ W2) {
    int i = blockIdx.x * blockDim.x + threadIdx.x;
    if (i < HID_C * IN_C) {
        int n = i >> 7, k = i & 127;
        g_W1T[n * IN_C + k] = to_tf32(W1[k * HID_C + n]);
    } else if (i < HID_C * IN_C + OUT_C * HID_C) {
        int j = i - HID_C * IN_C;
        int n = j >> 7, k = j & 127;
        g_W2T[n * HID_C + k] = to_tf32(W2[k * OUT_C + n]);
    }
}

// ----------------- tf32 mma.sync GEMM: C[M,NDIM] = A[M,128] @ BT[NDIM,128]^T
// BM=128, BN=NDIM, BK=32; 256 threads = 8 warps (4 along M x 2 along N)
// warp tile: 32 rows x (NDIM/2) cols -> 2 m-tiles (m16) x NT n-tiles (n8)
template <int NDIM>
__global__ __launch_bounds__(256) void gemm_mma_kernel(
    const float* __restrict__ A, const float* __restrict__ BT,
    float* __restrict__ C, int M)
{
    constexpr int BK = 32;
    constexpr int AS = 136;           // floats; 136 % 32 == 8 -> conflict-free frags
    constexpr int BS = NDIM + 8;      // 136 or 72; % 32 == 8
    constexpr int NT = NDIM / 16;     // n-tiles per warp: 8 (NDIM=128) / 4 (NDIM=64)

    __shared__ float As[BK * AS];     // [k][row]
    __shared__ float Bs[BK * BS];     // [k][n]

    int tid = threadIdx.x;
    int wid = tid >> 5;
    int lane = tid & 31;
    int wm = wid & 3;                 // warp m index (0..3)
    int wn = wid >> 2;                // warp n index (0..1)
    int warpRow = wm * 32;
    int warpCol = wn * (NDIM / 2);
    int rowBase = blockIdx.x * 128;

    float c[2][NT][4];
#pragma unroll
    for (int mt = 0; mt < 2; mt++)
#pragma unroll
        for (int nt = 0; nt < NT; nt++)
#pragma unroll
            for (int q = 0; q < 4; q++) c[mt][nt][q] = 0.0f;

    int lq = lane & 3;                // lane % 4
    int lg = lane >> 2;               // lane / 4 (group id)

    for (int k0 = 0; k0 < 128; k0 += BK) {
        // stage A chunk: 128 rows x 32 k, transpose to As[k][row], tf32-round
#pragma unroll
        for (int it = 0; it < 4; it++) {
            int idx = tid + it * 256;         // 0..1023
            int r = idx >> 3;                 // row 0..127
            int c4 = idx & 7;                 // float4 idx along k (0..7)
            float4 v = make_float4(0.f, 0.f, 0.f, 0.f);
            int gm = rowBase + r;
            if (gm < M) v = *(const float4*)&A[(size_t)gm * 128 + k0 + c4 * 4];
            int kk = c4 * 4;
            As[(kk + 0) * AS + r] = to_tf32(v.x);
            As[(kk + 1) * AS + r] = to_tf32(v.y);
            As[(kk + 2) * AS + r] = to_tf32(v.z);
            As[(kk + 3) * AS + r] = to_tf32(v.w);
        }
        // stage B chunk: NDIM rows x 32 k, transpose to Bs[k][n] (already tf32)
#pragma unroll
        for (int it = 0; it < NDIM / 32; it++) {
            int idx = tid + it * 256;
            int n = idx >> 3;
            int c4 = idx & 7;
            float4 v = *(const float4*)&BT[(size_t)n * 128 + k0 + c4 * 4];
            int kk = c4 * 4;
            Bs[(kk + 0) * BS + n] = v.x;
            Bs[(kk + 1) * BS + n] = v.y;
            Bs[(kk + 2) * BS + n] = v.z;
            Bs[(kk + 3) * BS + n] = v.w;
        }
        __syncthreads();

#pragma unroll
        for (int ks = 0; ks < BK / 8; ks++) {
            int kb = ks * 8 + lq;
            // A fragments: 2 m-tiles x 4 regs
            uint32_t af[2][4];
#pragma unroll
            for (int mt = 0; mt < 2; mt++) {
                int r0 = warpRow + mt * 16 + lg;
                af[mt][0] = __float_as_uint(As[kb * AS + r0]);
                af[mt][1] = __float_as_uint(As[kb * AS + r0 + 8]);
                af[mt][2] = __float_as_uint(As[(kb + 4) * AS + r0]);
                af[mt][3] = __float_as_uint(As[(kb + 4) * AS + r0 + 8]);
            }
            // B fragments: NT n-tiles x 2 regs
            uint32_t bf[NT][2];
#pragma unroll
            for (int nt = 0; nt < NT; nt++) {
                int n0 = warpCol + nt * 8 + lg;
                bf[nt][0] = __float_as_uint(Bs[kb * BS + n0]);
                bf[nt][1] = __float_as_uint(Bs[(kb + 4) * BS + n0]);
            }
#pragma unroll
            for (int mt = 0; mt < 2; mt++)
#pragma unroll
                for (int nt = 0; nt < NT; nt++)
                    mma_16x8x8(c[mt][nt], af[mt], bf[nt]);
        }
        __syncthreads();
    }

    // epilogue: c0/c1 -> (row, 2*lq / +1), c2/c3 -> (row+8, same cols)
#pragma unroll
    for (int mt = 0; mt < 2; mt++) {
        int r0 = rowBase + warpRow + mt * 16 + lg;
        int r1 = r0 + 8;
#pragma unroll
        for (int nt = 0; nt < NT; nt++) {
            int col = warpCol + nt * 8 + 2 * lq;
            if (r0 < M)
                *(float2*)&C[(size_t)r0 * NDIM + col] = make_float2(c[mt][nt][0], c[mt][nt][1]);
            if (r1 < M)
                *(float2*)&C[(size_t)r1 * NDIM + col] = make_float2(c[mt][nt][2], c[mt][nt][3]);
        }
    }
}

// ----------------- aggregation layer 1: bias + relu + dropout fused ---------
__global__ void agg1_kernel(const float* __restrict__ b1) {
    int w = (blockIdx.x * blockDim.x + threadIdx.x) >> 5;
    int lane = threadIdx.x & 31;
    if (w >= N_NODES) return;
    int n = w;

    float dn = g_dinv[n];
    const float4* h0 = (const float4*)g_h0;

    float4 a = h0[(size_t)n * 32 + lane];
    float wn = dn * dn;
    float4 acc = make_float4(a.x * wn, a.y * wn, a.z * wn, a.w * wn);

    int beg = g_rowptr[n], end = g_rowptr[n + 1];
    for (int k = beg; k < end; k++) {
        int s = g_adj[k];
        float we = g_dinv[s] * dn;
        float4 v = h0[(size_t)s * 32 + lane];
        acc.x = fmaf(we, v.x, acc.x);
        acc.y = fmaf(we, v.y, acc.y);
        acc.z = fmaf(we, v.z, acc.z);
        acc.w = fmaf(we, v.w, acc.w);
    }

    float4 bb = *(const float4*)&b1[lane * 4];
    acc.x = fmaxf(acc.x + bb.x, 0.0f);
    acc.y = fmaxf(acc.y + bb.y, 0.0f);
    acc.z = fmaxf(acc.z + bb.z, 0.0f);
    acc.w = fmaxf(acc.w + bb.w, 0.0f);

    uint32_t flat = (uint32_t)n * HID_C + lane * 4;
    acc.x = apply_dropout(acc.x, flat + 0);
    acc.y = apply_dropout(acc.y, flat + 1);
    acc.z = apply_dropout(acc.z, flat + 2);
    acc.w = apply_dropout(acc.w, flat + 3);

    ((float4*)g_h1)[(size_t)n * 32 + lane] = acc;
}

// ----------------- aggregation layer 2: bias fused, writes d_out ------------
__global__ void agg2_kernel(const float* __restrict__ b2, float* __restrict__ out) {
    int w = (blockIdx.x * blockDim.x + threadIdx.x) >> 5;
    int lane = threadIdx.x & 31;
    if (w >= N_NODES) return;
    int n = w;

    float dn = g_dinv[n];
    const float2* h2 = (const float2*)g_h2;

    float2 a = h2[(size_t)n * 32 + lane];
    float wn = dn * dn;
    float2 acc = make_float2(a.x * wn, a.y * wn);

    int beg = g_rowptr[n], end = g_rowptr[n + 1];
    for (int k = beg; k < end; k++) {
        int s = g_adj[k];
        float we = g_dinv[s] * dn;
        float2 v = h2[(size_t)s * 32 + lane];
        acc.x = fmaf(we, v.x, acc.x);
        acc.y = fmaf(we, v.y, acc.y);
    }

    float2 bb = *(const float2*)&b2[lane * 2];
    acc.x += bb.x;
    acc.y += bb.y;
    ((float2*)out)[(size_t)n * 32 + lane] = acc;
}

// ----------------- launch ----------------------------------------------------
extern "C" void kernel_launch(void* const* d_in, const int* in_sizes, int n_in,
                              void* d_out, int out_size) {
    const float* x  = (const float*)d_in[0];   // [50000,128]
    const float* W1 = (const float*)d_in[1];   // [128,128]
    const float* b1 = (const float*)d_in[2];   // [128]
    const float* W2 = (const float*)d_in[3];   // [128,64]
    const float* b2 = (const float*)d_in[4];   // [64]
    const void*  ei = (const void*)d_in[5];    // [2,600000] int32 or int64
    float* out = (float*)d_out;

    float* h0 = nullptr; cudaGetSymbolAddress((void**)&h0, g_h0);
    float* h1 = nullptr; cudaGetSymbolAddress((void**)&h1, g_h1);
    float* h2 = nullptr; cudaGetSymbolAddress((void**)&h2, g_h2);
    float* w1t = nullptr; cudaGetSymbolAddress((void**)&w1t, g_W1T);
    float* w2t = nullptr; cudaGetSymbolAddress((void**)&w2t, g_W2T);

    // graph build (launches 1-5)
    setup0_kernel<<<(N_NODES + 255) / 256, 256>>>((const int*)ei);
    convert_kernel<<<(N_EDGES + 255) / 256, 256>>>(ei);
    scan_kernel<<<1, 1024>>>();
    fill_kernel<<<(N_EDGES + 255) / 256, 256>>>();
    wtrans_kernel<<<(HID_C * IN_C + OUT_C * HID_C + 255) / 256, 256>>>(W1, W2);

    // layer 1 (launch 6 = profiled by ncu -s 5 -c 1)
    gemm_mma_kernel<128><<<(N_NODES + 127) / 128, 256>>>(x, w1t, h0, N_NODES);
    agg1_kernel<<<(N_NODES * 32 + 255) / 256, 256>>>(b1);

    // layer 2
    gemm_mma_kernel<64><<<(N_NODES + 127) / 128, 256>>>(h1, w2t, h2, N_NODES);
    agg2_kernel<<<(N_NODES * 32 + 255) / 256, 256>>>(b2, out);
}